// round 16
// baseline (speedup 1.0000x reference)
#include <cuda_runtime.h>
#include <cuda_bf16.h>
#include <math.h>

// Problem constants (fixed by the reference).
#define BATCH 4096
#define DIM   768
#define KNEG  60
#define NLOG  (KNEG + 1)      // 61 logits per row
#define CHUNKS 96             // DIM / 8 bf16-chunks of 16B
#define ROW_BYTES 1536        // one bf16 item row (768 * 2)

typedef unsigned long long u64;

// 16-byte chunk of 8 bf16 values, viewed as 4x bf16x2 words.
struct alignas(16) BF8 { unsigned u[4]; };

// Scratch (no device allocation allowed -> __device__ globals).
__device__ BF8       g_items_bf16[BATCH * CHUNKS];   // 6.29 MB bf16 item table
__device__ float     g_row_loss[BATCH];
__device__ unsigned  g_done = 0;                     // last-block ticket

// ---- dynamic-smem layout (bytes) ----
#define SM_TILE   0                                  // 61 rows x 1536 B
#define SM_MBAR   (NLOG * ROW_BYTES)                 // 93696 (8B aligned)
#define SM_IDX    (SM_MBAR + NLOG * 8)               // 94184
#define SM_LOGITS (SM_IDX + NLOG * 4)                // 94428
#define SM_RED    (SM_LOGITS + NLOG * 4)             // 94672
#define SM_LAST   (SM_RED + 256 * 4)                 // 95696
#define SM_TOTAL  (SM_LAST + 16)                     // 95712 -> 2 CTAs/SM

// ---- sm_103a packed-fp32 helpers (ptxas won't emit FFMA2 from plain C++) ----
__device__ __forceinline__ u64 pack_f32x2(float lo, float hi) {
    u64 r; asm("mov.b64 %0, {%1, %2};" : "=l"(r) : "f"(lo), "f"(hi)); return r;
}
// EXACT bf16x2 (hi16|lo16) -> f32x2: lo = w<<16, hi = w & 0xFFFF0000.
// (The unmasked-hi shortcut is a systematically-positive bias -> rejected R14.)
__device__ __forceinline__ u64 bf2_to_f32x2(unsigned w) {
    unsigned lo = w << 16, hi = w & 0xFFFF0000u;
    u64 r; asm("mov.b64 %0, {%1, %2};" : "=l"(r) : "r"(lo), "r"(hi)); return r;
}
__device__ __forceinline__ void ffma2(u64& d, u64 a, u64 b) {
    asm("fma.rn.f32x2 %0, %1, %2, %0;" : "+l"(d) : "l"(a), "l"(b));
}
__device__ __forceinline__ float hsum2(u64 a, u64 b) {
    u64 s; asm("add.rn.f32x2 %0, %1, %2;" : "=l"(s) : "l"(a), "l"(b));
    float lo, hi; asm("mov.b64 {%0, %1}, %2;" : "=f"(lo), "=f"(hi) : "l"(s));
    return lo + hi;
}
__device__ __forceinline__ unsigned pack_bf2(float x, float y) {
    __nv_bfloat162 t = __floats2bfloat162_rn(x, y);   // x -> low half
    return *reinterpret_cast<unsigned*>(&t);
}
__device__ __forceinline__ unsigned smem_u32(const void* p) {
    unsigned a;
    asm("{ .reg .u64 t; cvta.to.shared.u64 t, %1; cvt.u32.u64 %0, t; }"
        : "=r"(a) : "l"(p));
    return a;
}
__device__ __forceinline__ void mbar_init(unsigned mb, unsigned cnt) {
    asm volatile("mbarrier.init.shared.b64 [%0], %1;" :: "r"(mb), "r"(cnt)
                 : "memory");
}
__device__ __forceinline__ void mbar_wait0(unsigned mb) {   // parity 0, acquire
    asm volatile(
        "{\n\t.reg .pred P;\n\t"
        "WL_%=:\n\t"
        "mbarrier.try_wait.parity.acquire.cta.shared::cta.b64 P, [%0], 0, 0x989680;\n\t"
        "@P bra.uni WD_%=;\n\t"
        "bra.uni WL_%=;\n\t"
        "WD_%=:\n\t}"
        :: "r"(mb) : "memory");
}

// ---------------------------------------------------------------------------
// Kernel 1: convert the fp32 item table to bf16 (DRAM-bound, ~2.4us).
// ---------------------------------------------------------------------------
__global__ __launch_bounds__(256)
void convert_items_kernel(const float* __restrict__ items)
{
    const unsigned t = blockIdx.x * 256u + threadIdx.x;   // chunk id
    const float4* in = reinterpret_cast<const float4*>(items);
    float4 a = in[2u * t];
    float4 b = in[2u * t + 1u];
    BF8 o;
    o.u[0] = pack_bf2(a.x, a.y);
    o.u[1] = pack_bf2(a.z, a.w);
    o.u[2] = pack_bf2(b.x, b.y);
    o.u[3] = pack_bf2(b.z, b.w);
    g_items_bf16[t] = o;
}

// ---------------------------------------------------------------------------
// Kernel 2: one CTA per row. All 61 gathered bf16 item rows are staged into
// dynamic smem via cp.async.bulk (UBLKCP) with one mbarrier per row ->
// prefetch depth 61 at zero register cost. Warp w consumes logits
// {w, w+8, ...} from smem (conflict-free LDS.128). MACs = packed fp32x2
// FFMA; u[b] slice register-resident. Fused last-block mean.
// ---------------------------------------------------------------------------
__global__ __launch_bounds__(256)
void u2i_row_kernel(const float* __restrict__ user,
                    const int*   __restrict__ negs,
                    float*       __restrict__ out)
{
    extern __shared__ char smem[];
    const unsigned sbase = smem_u32(smem);

    const int b    = blockIdx.x;
    const int tid  = threadIdx.x;
    const int warp = tid >> 5;
    const int lane = tid & 31;

    int*   s_idx    = reinterpret_cast<int*>  (smem + SM_IDX);
    float* s_logits = reinterpret_cast<float*>(smem + SM_LOGITS);
    float* s_red    = reinterpret_cast<float*>(smem + SM_RED);
    int*   s_last   = reinterpret_cast<int*>  (smem + SM_LAST);

    // Indices (logit 0 = own positive row) + per-row mbarriers.
    if (tid == 0)          s_idx[0]   = b;
    else if (tid <= KNEG)  s_idx[tid] = negs[b * KNEG + (tid - 1)];
    if (tid < NLOG)
        mbar_init(sbase + SM_MBAR + tid * 8, 1);
    __syncthreads();

    // Each warp's lane 0 issues async bulk copies for its rows: expect_tx
    // then cp.async.bulk (complete_tx flips the per-row barrier).
    if (lane == 0) {
        for (int j = warp; j < NLOG; j += 8) {
            const unsigned mb  = sbase + SM_MBAR + j * 8;
            const unsigned dst = sbase + SM_TILE + j * ROW_BYTES;
            const char* src = reinterpret_cast<const char*>(g_items_bf16)
                            + (size_t)s_idx[j] * ROW_BYTES;
            asm volatile(
                "mbarrier.arrive.expect_tx.shared::cta.b64 _, [%0], %1;"
                :: "r"(mb), "r"((unsigned)ROW_BYTES) : "memory");
            asm volatile(
                "cp.async.bulk.shared::cta.global.mbarrier::complete_tx::bytes "
                "[%0], [%1], %2, [%3];"
                :: "r"(dst), "l"(src), "r"((unsigned)ROW_BYTES), "r"(mb)
                : "memory");
        }
    }

    // Lane's fixed 24-element u-slice as 12 packed f32x2 registers
    // (overlaps with the in-flight bulk copies).
    const float4* u4 = reinterpret_cast<const float4*>(user + (size_t)b * DIM);
    u64 uu[12];
#pragma unroll
    for (int i = 0; i < 3; i++) {
        const int c = lane + 32 * i;
        float4 a = u4[2 * c];
        float4 d = u4[2 * c + 1];
        uu[4 * i + 0] = pack_f32x2(a.x, a.y);
        uu[4 * i + 1] = pack_f32x2(a.z, a.w);
        uu[4 * i + 2] = pack_f32x2(d.x, d.y);
        uu[4 * i + 3] = pack_f32x2(d.z, d.w);
    }

    // Consume: warp w handles logits {w, w+8, ...} in arrival-pipeline order.
    for (int j = warp; j < NLOG; j += 8) {
        mbar_wait0(sbase + SM_MBAR + j * 8);
        const uint4* t = reinterpret_cast<const uint4*>(smem + SM_TILE
                                                        + (size_t)j * ROW_BYTES);
        uint4 r0 = t[lane];            // conflict-free LDS.128 (16B stride)
        uint4 r1 = t[lane + 32];
        uint4 r2 = t[lane + 64];

        u64 accA = 0ull, accB = 0ull;  // two chains halve FFMA2 dep latency
        ffma2(accA, bf2_to_f32x2(r0.x), uu[0]);
        ffma2(accB, bf2_to_f32x2(r0.y), uu[1]);
        ffma2(accA, bf2_to_f32x2(r0.z), uu[2]);
        ffma2(accB, bf2_to_f32x2(r0.w), uu[3]);
        ffma2(accA, bf2_to_f32x2(r1.x), uu[4]);
        ffma2(accB, bf2_to_f32x2(r1.y), uu[5]);
        ffma2(accA, bf2_to_f32x2(r1.z), uu[6]);
        ffma2(accB, bf2_to_f32x2(r1.w), uu[7]);
        ffma2(accA, bf2_to_f32x2(r2.x), uu[8]);
        ffma2(accB, bf2_to_f32x2(r2.y), uu[9]);
        ffma2(accA, bf2_to_f32x2(r2.z), uu[10]);
        ffma2(accB, bf2_to_f32x2(r2.w), uu[11]);

        float a1 = hsum2(accA, accB);
#pragma unroll
        for (int off = 16; off; off >>= 1)
            a1 += __shfl_xor_sync(0xffffffffu, a1, off);
        if (lane == 0) s_logits[j] = a1;
    }
    __syncthreads();

    // Warp 0: 61-way logsumexp, loss = lse - logit[0]; then take a ticket.
    if (warp == 0) {
        const float NEG = -3.0e38f;              // expf underflows to 0
        float a = (lane      < NLOG) ? s_logits[lane]      : NEG;
        float c = (lane + 32 < NLOG) ? s_logits[lane + 32] : NEG;

        float m = fmaxf(a, c);
#pragma unroll
        for (int off = 16; off; off >>= 1)
            m = fmaxf(m, __shfl_xor_sync(0xffffffffu, m, off));

        float s = expf(a - m) + expf(c - m);
#pragma unroll
        for (int off = 16; off; off >>= 1)
            s += __shfl_xor_sync(0xffffffffu, s, off);

        if (lane == 0) {
            g_row_loss[b] = m + logf(s) - s_logits[0];
            __threadfence();
            s_last[0] = (atomicAdd(&g_done, 1u) == BATCH - 1u) ? 1 : 0;
        }
    }
    __syncthreads();

    // Last block to finish: deterministic fixed-order mean over all rows.
    if (s_last[0]) {
        __threadfence();
        float s = 0.0f;
        for (int i = tid; i < BATCH; i += 256)
            s += __ldcg(&g_row_loss[i]);
        s_red[tid] = s;
        __syncthreads();
#pragma unroll
        for (int st = 128; st; st >>= 1) {
            if (tid < st) s_red[tid] += s_red[tid + st];
            __syncthreads();
        }
        if (tid == 0) {
            out[0] = s_red[0] * (1.0f / (float)BATCH);
            g_done = 0;                          // reset for next graph replay
        }
    }
}

// ---------------------------------------------------------------------------
// Harness entry point. Inputs per metadata order:
//   d_in[0] = user_emb     f32 (4096*768)
//   d_in[1] = pos_item_emb f32 (4096*768)
//   d_in[2] = neg_indices  i32 (4096*60)
// d_out = f32 scalar.  Graph-capturable: two launches, no sync, no alloc.
// ---------------------------------------------------------------------------
extern "C" void kernel_launch(void* const* d_in, const int* in_sizes, int n_in,
                              void* d_out, int out_size)
{
    (void)in_sizes; (void)n_in; (void)out_size;
    const float* user  = (const float*)d_in[0];
    const float* items = (const float*)d_in[1];
    const int*   negs  = (const int*)  d_in[2];
    float*       out   = (float*)      d_out;

    // 96KB dynamic smem (> 48KB default) requires an explicit opt-in.
    // Host-side attribute set; idempotent and graph-capture-safe.
    cudaFuncSetAttribute(u2i_row_kernel,
                         cudaFuncAttributeMaxDynamicSharedMemorySize, SM_TOTAL);

    convert_items_kernel<<<(BATCH * CHUNKS) / 256, 256>>>(items);
    u2i_row_kernel<<<BATCH, 256, SM_TOTAL>>>(user, negs, out);
}